// round 6
// baseline (speedup 1.0000x reference)
#include <cuda_runtime.h>
#include <math.h>

#define N_USERS      100000
#define N_ITEMS      50000
#define N_ENTITIES   180000
#define N_USER_NODES 150000
#define N_REL        32
#define D            64
#define DV4          16   // D/4 float4 chunks per row

// ---------------- scratch (device globals; no allocation allowed) ----------
__device__ float g_eagg[(size_t)N_ENTITIES * D];      // entity_agg sums
__device__ float g_aagg[(size_t)N_USER_NODES * D];    // attribute_agg sums
__device__ float g_iu  [(size_t)N_ITEMS * D];         // i_u_agg sums
__device__ float g_ui  [(size_t)N_USERS * D];         // u_i_agg sums
__device__ float g_cnt_e [N_ENTITIES];
__device__ float g_cnt_a [N_USER_NODES];
__device__ float g_cnt_iu[N_ITEMS];
__device__ float g_cnt_ui[N_USERS];

// ---------------- zero scratch each launch ---------------------------------
__global__ void zero_all() {
    int gid = blockIdx.x * blockDim.x + threadIdx.x;
    int stride = gridDim.x * blockDim.x;
    float4 z = make_float4(0.f, 0.f, 0.f, 0.f);
#define ZLOOP(arr, n4) { float4* p = (float4*)(arr); \
    for (int i = gid; i < (n4); i += stride) p[i] = z; }
    ZLOOP(g_eagg, N_ENTITIES * DV4)
    ZLOOP(g_aagg, N_USER_NODES * DV4)
    ZLOOP(g_iu,   N_ITEMS * DV4)
    ZLOOP(g_ui,   N_USERS * DV4)
    ZLOOP(g_cnt_e,  N_ENTITIES / 4)
    ZLOOP(g_cnt_a,  N_USER_NODES / 4)
    ZLOOP(g_cnt_iu, N_ITEMS / 4)
    ZLOOP(g_cnt_ui, N_USERS / 4)
#undef ZLOOP
}

// ---------------- typed scatter: agg[head] += emb[tail] * weight[type] -----
// 16 lanes per edge, one float4 chunk each. Chunk id invariant across the
// grid-stride loop (stride multiple of 16).
__device__ __forceinline__ void scatter_body(
    const float4* __restrict__ emb, const float4* __restrict__ sw,
    const int* __restrict__ head, const int* __restrict__ tail,
    const int* __restrict__ etype,
    float4* __restrict__ agg, float* __restrict__ cnt, int n_edges)
{
    int gid = blockIdx.x * blockDim.x + threadIdx.x;
    int c = gid & 15;
    int stride = gridDim.x * blockDim.x;
    int total = n_edges << 4;
    for (int g = gid; g < total; g += stride) {
        int e  = g >> 4;
        int h  = __ldg(head + e);
        int t  = __ldg(tail + e);
        int ty = __ldg(etype + e);
        float4 v = __ldg(emb + t * DV4 + c);
        float4 w = sw[ty * DV4 + c];
        atomicAdd(agg + h * DV4 + c,
                  make_float4(v.x * w.x, v.y * w.y, v.z * w.z, v.w * w.w));
        if (c == 0) atomicAdd(cnt + h, 1.0f);
    }
}

__global__ void scatter_entity(const float4* __restrict__ emb,
                               const float4* __restrict__ weight,
                               const int* __restrict__ head,
                               const int* __restrict__ tail,
                               const int* __restrict__ etype, int n)
{
    __shared__ float4 sw[N_REL * DV4];
    for (int i = threadIdx.x; i < N_REL * DV4; i += blockDim.x)
        sw[i] = __ldg(weight + i);
    __syncthreads();
    scatter_body(emb, sw, head, tail, etype, (float4*)g_eagg, g_cnt_e, n);
}

__global__ void scatter_userkg(const float4* __restrict__ emb,
                               const float4* __restrict__ weight,
                               const int* __restrict__ head,
                               const int* __restrict__ tail,
                               const int* __restrict__ etype, int n)
{
    __shared__ float4 sw[N_REL * DV4];
    for (int i = threadIdx.x; i < N_REL * DV4; i += blockDim.x)
        sw[i] = __ldg(weight + i);
    __syncthreads();
    scatter_body(emb, sw, head, tail, etype, (float4*)g_aagg, g_cnt_a, n);
}

// ---------------- fused interaction-matrix scatters -------------------------
// i_u_agg[mat_col] += user_emb[mat_row]   * weight[0]
// u_i_agg[mat_row] += entity_emb[mat_col] * weight[0]
__global__ void scatter_mat(const float4* __restrict__ uemb,
                            const float4* __restrict__ eemb,
                            const float4* __restrict__ weight,
                            const int* __restrict__ mrow,
                            const int* __restrict__ mcol, int n)
{
    int gid = blockIdx.x * blockDim.x + threadIdx.x;
    int c = gid & 15;
    int stride = gridDim.x * blockDim.x;
    float4 w0 = __ldg(weight + c);          // weight[0] chunk, loop-invariant
    float4* iu = (float4*)g_iu;
    float4* ui = (float4*)g_ui;
    int total = n << 4;
    for (int g = gid; g < total; g += stride) {
        int e  = g >> 4;
        int r  = __ldg(mrow + e);   // user index  (< N_USERS)
        int cl = __ldg(mcol + e);   // item index  (< N_ITEMS)
        float4 uv = __ldg(uemb + r  * DV4 + c);
        float4 ev = __ldg(eemb + cl * DV4 + c);
        atomicAdd(iu + cl * DV4 + c,
                  make_float4(uv.x * w0.x, uv.y * w0.y, uv.z * w0.z, uv.w * w0.w));
        atomicAdd(ui + r * DV4 + c,
                  make_float4(ev.x * w0.x, ev.y * w0.y, ev.z * w0.z, ev.w * w0.w));
        if (c == 0) {
            atomicAdd(g_cnt_iu + cl, 1.0f);
            atomicAdd(g_cnt_ui + r,  1.0f);
        }
    }
}

// ---------------- gated fusion: sigmoid(A@GA^T + B@GB^T) blend --------------
// MODE 0 (items): A = entity_agg[:N_ITEMS]/cnt, B = i_u_agg/cnt,
//                 GA = gate1, GB = gate2, out = g*A + (1-g)*B
// MODE 1 (users): A = u_i_agg/cnt, B = attr_agg[:N_USERS]/cnt,
//                 GA = gate2, GB = gate3, out = g*B + (1-g)*A
// Implemented as one K=128 GEMM:  Z = [A|B] @ [GA^T ; GB^T]
// 64-row tile / block, 256 threads, 4x4 register tiles, stride-68 padded smem.
#define GPAD 68
#define GATE_SMEM ((2 * 128 * GPAD + 128) * 4)

template <int MODE>
__global__ void gate_fuse(const float* __restrict__ GA,
                          const float* __restrict__ GB,
                          float* __restrict__ out, int nrows)
{
    const float* aggA = (MODE == 0) ? g_eagg   : g_ui;
    const float* cntA = (MODE == 0) ? g_cnt_e  : g_cnt_ui;
    const float* aggB = (MODE == 0) ? g_iu     : g_aagg;
    const float* cntB = (MODE == 0) ? g_cnt_iu : g_cnt_a;

    extern __shared__ float sm[];
    float* As   = sm;                    // [128][GPAD]  (A|B transposed, normalized)
    float* Gs   = sm + 128 * GPAD;       // [128][GPAD]  (GA^T ; GB^T)
    float* invA = Gs + 128 * GPAD;       // [64]
    float* invB = invA + 64;             // [64]

    int tid = threadIdx.x;
    int row0 = blockIdx.x * 64;

    if (tid < 64) {
        int r = row0 + tid;
        invA[tid] = (r < nrows) ? 1.f / fmaxf(__ldg(cntA + r), 1.f) : 0.f;
    } else if (tid < 128) {
        int r = row0 + tid - 64;
        invB[tid - 64] = (r < nrows) ? 1.f / fmaxf(__ldg(cntB + r), 1.f) : 0.f;
    }
    __syncthreads();

    for (int idx = tid; idx < 64 * 64; idx += 256) {
        int r = idx >> 6, k = idx & 63;
        int row = row0 + r;
        float a = 0.f, b = 0.f;
        if (row < nrows) {
            a = aggA[(size_t)row * D + k] * invA[r];
            b = aggB[(size_t)row * D + k] * invB[r];
        }
        As[k * GPAD + r]        = a;
        As[(k + 64) * GPAD + r] = b;
    }
    for (int idx = tid; idx < 64 * 64; idx += 256) {
        int j = idx >> 6, k = idx & 63;          // GA[j*64+k] read coalesced
        Gs[k * GPAD + j]        = __ldg(GA + idx);
        Gs[(k + 64) * GPAD + j] = __ldg(GB + idx);
    }
    __syncthreads();

    int tx = tid & 15, ty = tid >> 4;
    float acc[4][4] = {};
    const float4* As4 = (const float4*)As;
    const float4* Gs4 = (const float4*)Gs;
#pragma unroll 4
    for (int k = 0; k < 128; k++) {
        float4 av = As4[k * (GPAD / 4) + ty];
        float4 gv = Gs4[k * (GPAD / 4) + tx];
        float a_[4] = {av.x, av.y, av.z, av.w};
        float g_[4] = {gv.x, gv.y, gv.z, gv.w};
#pragma unroll
        for (int i = 0; i < 4; i++)
#pragma unroll
            for (int j = 0; j < 4; j++)
                acc[i][j] += a_[i] * g_[j];
    }

#pragma unroll
    for (int i = 0; i < 4; i++) {
        int r = ty * 4 + i;
        int row = row0 + r;
        if (row >= nrows) continue;
        float4 o;
        float* op = &o.x;
#pragma unroll
        for (int j = 0; j < 4; j++) {
            int col = tx * 4 + j;
            float gate = 1.f / (1.f + __expf(-acc[i][j]));
            float a = As[col * GPAD + r];
            float b = As[(col + 64) * GPAD + r];
            op[j] = (MODE == 1) ? (gate * b + (1.f - gate) * a)
                                : (gate * a + (1.f - gate) * b);
        }
        *(float4*)(out + (size_t)row * D + tx * 4) = o;
    }
}

// ---------------- tail rows: out = agg / max(cnt, 1) ------------------------
template <int MODE>
__global__ void normalize_rows(float* __restrict__ out, int row0, int row_end)
{
    const float* agg = (MODE == 0) ? g_eagg  : g_aagg;
    const float* cnt = (MODE == 0) ? g_cnt_e : g_cnt_a;
    int gid = blockIdx.x * blockDim.x + threadIdx.x;
    int n = (row_end - row0) * DV4;
    if (gid >= n) return;
    int r = row0 + (gid >> 4);
    int c = gid & 15;
    float ic = 1.f / fmaxf(__ldg(cnt + r), 1.f);
    float4 v = ((const float4*)agg)[(size_t)r * DV4 + c];
    ((float4*)out)[(size_t)r * DV4 + c] =
        make_float4(v.x * ic, v.y * ic, v.z * ic, v.w * ic);
}

// ---------------- launch -----------------------------------------------------
extern "C" void kernel_launch(void* const* d_in, const int* in_sizes, int n_in,
                              void* d_out, int out_size)
{
    const float* entity_emb = (const float*)d_in[0];
    const float* user_emb   = (const float*)d_in[1];
    const float* weight     = (const float*)d_in[2];
    const float* gate1_w    = (const float*)d_in[3];
    const float* gate2_w    = (const float*)d_in[4];
    const float* gate3_w    = (const float*)d_in[5];
    const int*   edge_index = (const int*)d_in[6];
    const int*   edge_type  = (const int*)d_in[7];
    const int*   uedge_index= (const int*)d_in[8];
    const int*   uedge_type = (const int*)d_in[9];
    const int*   mat_row    = (const int*)d_in[10];
    const int*   mat_col    = (const int*)d_in[11];

    int n_e  = in_sizes[7];    // 1,500,000
    int n_ue = in_sizes[9];    // 1,000,000
    int n_m  = in_sizes[10];   // 1,500,000

    float* out = (float*)d_out;
    float* user_out = out + (size_t)N_ENTITIES * D;

    // opt-in >48KB dynamic smem (idempotent, capture-safe: no stream work)
    cudaFuncSetAttribute(gate_fuse<0>, cudaFuncAttributeMaxDynamicSharedMemorySize, GATE_SMEM);
    cudaFuncSetAttribute(gate_fuse<1>, cudaFuncAttributeMaxDynamicSharedMemorySize, GATE_SMEM);

    zero_all<<<2048, 256>>>();

    const int SG = 4736;   // 32 blocks/SM worth of grid-stride scatter blocks
    scatter_entity<<<SG, 256>>>((const float4*)entity_emb, (const float4*)weight,
                                edge_index, edge_index + n_e, edge_type, n_e);
    scatter_userkg<<<SG, 256>>>((const float4*)user_emb, (const float4*)weight,
                                uedge_index, uedge_index + n_ue, uedge_type, n_ue);
    scatter_mat<<<SG, 256>>>((const float4*)user_emb, (const float4*)entity_emb,
                             (const float4*)weight, mat_row, mat_col, n_m);

    gate_fuse<0><<<(N_ITEMS + 63) / 64, 256, GATE_SMEM>>>(gate1_w, gate2_w, out, N_ITEMS);
    gate_fuse<1><<<(N_USERS + 63) / 64, 256, GATE_SMEM>>>(gate2_w, gate3_w, user_out, N_USERS);

    {
        int n = (N_ENTITIES - N_ITEMS) * DV4;
        normalize_rows<0><<<(n + 255) / 256, 256>>>(out, N_ITEMS, N_ENTITIES);
    }
    {
        int n = (N_USER_NODES - N_USERS) * DV4;
        normalize_rows<1><<<(n + 255) / 256, 256>>>(user_out, N_USERS, N_USER_NODES);
    }
}